// round 1
// baseline (speedup 1.0000x reference)
#include <cuda_runtime.h>
#include <cstdint>

// Problem dims (fixed by the dataset)
#define TOK   2048
#define CDIM  2048
#define NHEAD 32
#define DDIM  64
#define KR    1024     // routing vocab (q/k/v all 1024)

// Tiling
#define TT   64        // tokens per block
#define KC   64        // routing columns per shared chunk
#define PIT  68        // shared pitch in floats (mult of 4, avoids 32-bank wrap)

// Routed token ids, produced by kernel 1, consumed by kernel 2.
__device__ int g_qid[NHEAD * TOK];
__device__ int g_kid[NHEAD * TOK];
__device__ int g_vid[NHEAD * TOK];

static __device__ __forceinline__ uint32_t s2u(const void* p) {
    uint32_t a;
    asm("{ .reg .u64 t; cvta.to.shared.u64 t, %1; cvt.u32.u64 %0, t; }"
        : "=r"(a) : "l"(p));
    return a;
}
// 16B shared load -> two packed f32x2 (four consecutive floats = 4 tokens)
static __device__ __forceinline__ void lds_x2(uint64_t &a, uint64_t &b, uint32_t addr) {
    asm volatile("ld.shared.v2.b64 {%0,%1}, [%2];" : "=l"(a), "=l"(b) : "r"(addr));
}
static __device__ __forceinline__ void lds_w2(float &a, float &b, uint32_t addr) {
    asm volatile("ld.shared.v2.f32 {%0,%1}, [%2];" : "=f"(a), "=f"(b) : "r"(addr));
}
// broadcast one float into both lanes of an f32x2
static __device__ __forceinline__ uint64_t dup2(float f) {
    uint64_t r; asm("mov.b64 %0, {%1, %1};" : "=l"(r) : "f"(f)); return r;
}
// packed dual fp32 FMA (Blackwell f32x2 pipe; ptxas never emits this from C++)
static __device__ __forceinline__ uint64_t fma2(uint64_t a, uint64_t b, uint64_t c) {
    uint64_t d; asm("fma.rn.f32x2 %0, %1, %2, %3;" : "=l"(d) : "l"(a), "l"(b), "l"(c));
    return d;
}

// ---------------------------------------------------------------------------
// Kernel 1: fused argmax-GEMM for q/k/v routing.
// grid = (TOK/TT, NHEAD), block = 256.
// Thread org: ty = tid>>5 (8 groups of 8 tokens), tx = tid&31 (2 cols each).
// ---------------------------------------------------------------------------
__global__ __launch_bounds__(256) void route_argmax_kernel(
    const float* __restrict__ x, const float* __restrict__ wq,
    const float* __restrict__ wk, const float* __restrict__ wv)
{
    __shared__ float xsT[DDIM * PIT];   // x transposed: [d][token]
    __shared__ float wsT[DDIM * PIT];   // w chunk transposed: [d][col]

    const int m   = blockIdx.y;
    const int t0  = blockIdx.x * TT;
    const int tid = threadIdx.x;
    const int tx  = tid & 31;
    const int ty  = tid >> 5;

    // Stage X tile [TT tokens][64 d] transposed into shared.
    for (int i = tid; i < TT * 16; i += 256) {
        int t = i >> 4, dg = i & 15;
        float4 v = *reinterpret_cast<const float4*>(
            x + (size_t)(t0 + t) * CDIM + m * DDIM + dg * 4);
        xsT[(dg * 4 + 0) * PIT + t] = v.x;
        xsT[(dg * 4 + 1) * PIT + t] = v.y;
        xsT[(dg * 4 + 2) * PIT + t] = v.z;
        xsT[(dg * 4 + 3) * PIT + t] = v.w;
    }

    const uint32_t xbase = s2u(xsT) + (uint32_t)(ty * 8) * 4u;
    const uint32_t wbase = s2u(wsT) + (uint32_t)(tx * 2) * 4u;

    #pragma unroll
    for (int mat = 0; mat < 3; ++mat) {
        const float* W = ((mat == 0) ? wq : (mat == 1) ? wk : wv)
                         + (size_t)m * KR * DDIM;
        int* G = (mat == 0) ? g_qid : (mat == 1) ? g_kid : g_vid;

        float bmax[8];
        int   bidx[8];
        #pragma unroll
        for (int r = 0; r < 8; ++r) { bmax[r] = -3.402823466e38f; bidx[r] = 0; }

        for (int ch = 0; ch < KR / KC; ++ch) {
            __syncthreads();   // protect wsT reuse (and first-iter X staging)
            for (int i = tid; i < KC * 16; i += 256) {
                int k = i >> 4, dg = i & 15;
                float4 v = *reinterpret_cast<const float4*>(
                    W + (size_t)(ch * KC + k) * DDIM + dg * 4);
                wsT[(dg * 4 + 0) * PIT + k] = v.x;
                wsT[(dg * 4 + 1) * PIT + k] = v.y;
                wsT[(dg * 4 + 2) * PIT + k] = v.z;
                wsT[(dg * 4 + 3) * PIT + k] = v.w;
            }
            __syncthreads();

            uint64_t acc[4][2];   // 4 token-pairs x 2 cols, packed f32x2
            #pragma unroll
            for (int p = 0; p < 4; ++p) { acc[p][0] = 0ull; acc[p][1] = 0ull; }

            #pragma unroll 16
            for (int d = 0; d < DDIM; ++d) {
                uint64_t x0, x1, x2, x3;
                lds_x2(x0, x1, xbase + (uint32_t)d * (PIT * 4));
                lds_x2(x2, x3, xbase + (uint32_t)d * (PIT * 4) + 16);
                float f0, f1;
                lds_w2(f0, f1, wbase + (uint32_t)d * (PIT * 4));
                uint64_t w0 = dup2(f0), w1 = dup2(f1);
                acc[0][0] = fma2(x0, w0, acc[0][0]); acc[0][1] = fma2(x0, w1, acc[0][1]);
                acc[1][0] = fma2(x1, w0, acc[1][0]); acc[1][1] = fma2(x1, w1, acc[1][1]);
                acc[2][0] = fma2(x2, w0, acc[2][0]); acc[2][1] = fma2(x2, w1, acc[2][1]);
                acc[3][0] = fma2(x3, w0, acc[3][0]); acc[3][1] = fma2(x3, w1, acc[3][1]);
            }

            // Update running argmax (ascending col order -> strict '>' keeps
            // the first occurrence, matching jnp.argmax).
            #pragma unroll
            for (int p = 0; p < 4; ++p) {
                #pragma unroll
                for (int c = 0; c < 2; ++c) {
                    int col = ch * KC + tx * 2 + c;
                    float lo = __uint_as_float((uint32_t)acc[p][c]);
                    float hi = __uint_as_float((uint32_t)(acc[p][c] >> 32));
                    if (lo > bmax[2 * p])     { bmax[2 * p]     = lo; bidx[2 * p]     = col; }
                    if (hi > bmax[2 * p + 1]) { bmax[2 * p + 1] = hi; bidx[2 * p + 1] = col; }
                }
            }
        }

        // Reduce argmax across the 32 column-lanes (tie -> smaller index).
        #pragma unroll
        for (int r = 0; r < 8; ++r) {
            #pragma unroll
            for (int off = 16; off > 0; off >>= 1) {
                float om = __shfl_xor_sync(0xffffffffu, bmax[r], off, 32);
                int   oi = __shfl_xor_sync(0xffffffffu, bidx[r], off, 32);
                if (om > bmax[r] || (om == bmax[r] && oi < bidx[r])) {
                    bmax[r] = om; bidx[r] = oi;
                }
            }
        }
        if (tx == 0) {
            #pragma unroll
            for (int r = 0; r < 8; ++r)
                G[m * TOK + t0 + ty * 8 + r] = bidx[r];
        }
    }
}

// ---------------------------------------------------------------------------
// Kernel 2: causal last-occurrence match (tau) + embedding gather.
// tau[t] = max{ t' < t : k[t'] == q[t] } computed by independent backward
// scans (no sequential dependency). grid = NHEAD, block = 256.
// ---------------------------------------------------------------------------
__global__ __launch_bounds__(256) void tau_gather_kernel(
    const float* __restrict__ emb, float* __restrict__ out)
{
    __shared__ int sk[TOK];     // k ids for this head
    __shared__ int srow[TOK];   // final emb row per token (0 = invalid/pad)

    const int m   = blockIdx.x;
    const int tid = threadIdx.x;

    for (int i = tid; i < TOK; i += 256) sk[i] = g_kid[m * TOK + i];
    __syncthreads();

    for (int i = tid; i < TOK; i += 256) {
        int q = g_qid[m * TOK + i];
        int row = 0;
        for (int tp = i - 1; tp >= 0; --tp) {
            if (sk[tp] == q) { row = g_vid[m * TOK + tp] + 1; break; }
        }
        srow[i] = row;
    }
    __syncthreads();

    const float* E = emb + (size_t)m * (KR + 1) * DDIM;
    for (int j = tid; j < TOK * 16; j += 256) {
        int t = j >> 4, dg = j & 15;
        int row = srow[t];
        float4 v;
        if (row) {
            v = *reinterpret_cast<const float4*>(E + (size_t)row * DDIM + dg * 4);
        } else {
            v = make_float4(0.f, 0.f, 0.f, 0.f);   // padding row is zero
        }
        *reinterpret_cast<float4*>(out + (size_t)t * CDIM + m * DDIM + dg * 4) = v;
    }
}

// ---------------------------------------------------------------------------
extern "C" void kernel_launch(void* const* d_in, const int* in_sizes, int n_in,
                              void* d_out, int out_size)
{
    (void)in_sizes; (void)n_in; (void)out_size;
    const float* x   = (const float*)d_in[0];
    const float* wq  = (const float*)d_in[1];
    const float* wk  = (const float*)d_in[2];
    const float* wv  = (const float*)d_in[3];
    const float* emb = (const float*)d_in[4];
    float* out = (float*)d_out;

    dim3 g1(TOK / TT, NHEAD);
    route_argmax_kernel<<<g1, 256>>>(x, wq, wk, wv);
    tau_gather_kernel<<<NHEAD, 256>>>(emb, out);
}

// round 2
// speedup vs baseline: 1.0852x; 1.0852x over previous
#include <cuda_runtime.h>
#include <cstdint>

#define TOK   2048
#define CDIM  2048
#define NHEAD 32
#define DDIM  64
#define KR    1024

#define TT    128     // tokens per block (route)
#define KC    64      // routing cols per chunk (route)

__device__ int g_qid[NHEAD * TOK];
__device__ int g_kid[NHEAD * TOK];
__device__ int g_vid[NHEAD * TOK];
__device__ int g_row[NHEAD * TOK];

// packed dual fp32 FMA (Blackwell f32x2; ptxas never emits from C++)
static __device__ __forceinline__ uint64_t fma2(uint64_t a, uint64_t b, uint64_t c) {
    uint64_t d; asm("fma.rn.f32x2 %0, %1, %2, %3;" : "=l"(d) : "l"(a), "l"(b), "l"(c));
    return d;
}
static __device__ __forceinline__ uint64_t dup2(float f) {
    uint64_t r; asm("mov.b64 %0, {%1, %1};" : "=l"(r) : "f"(f)); return r;
}

// ---------------------------------------------------------------------------
// Kernel 1: fused argmax-GEMM routing.
// grid = (TOK/TT, NHEAD), block = 256 (8 warps).
// Warp tile: 16 tokens x 64 cols. Lane (tr=lane>>3, cr=lane&7): 4 tok x 8 cols.
// x smem: [d][token] pitch TT (LDS.128, 4 distinct 16B per warp -> 1 wf).
// w smem: [d][col] with group-of-8 XOR swizzle  col_group ^ ((d>>2)&7)
//         -> compute loads are 2x 16B packed col-pairs (1 wf each),
//         -> staging STS conflicts reduced 16-way -> 4-way.
// Next w chunk prefetched into registers during compute.
// ---------------------------------------------------------------------------
__global__ __launch_bounds__(256) void route_kernel(
    const float* __restrict__ x, const float* __restrict__ wq,
    const float* __restrict__ wk, const float* __restrict__ wv)
{
    __shared__ float xsT[DDIM * TT];   // 32 KB
    __shared__ float wsS[DDIM * KC];   // 16 KB  (total 48 KB exactly)

    const int tid  = threadIdx.x;
    const int lane = tid & 31;
    const int wid  = tid >> 5;
    const int tr   = lane >> 3;
    const int cr   = lane & 7;
    const int m    = blockIdx.y;
    const int t0   = blockIdx.x * TT;

    // stage x tile transposed (one-time; STS conflicts are amortized)
    for (int i = tid; i < TT * (DDIM / 4); i += 256) {
        int t = i >> 4, dg = i & 15;
        float4 v = *reinterpret_cast<const float4*>(
            x + (size_t)(t0 + t) * CDIM + m * DDIM + dg * 4);
        xsT[(dg * 4 + 0) * TT + t] = v.x;
        xsT[(dg * 4 + 1) * TT + t] = v.y;
        xsT[(dg * 4 + 2) * TT + t] = v.z;
        xsT[(dg * 4 + 3) * TT + t] = v.w;
    }

    const int wtok = wid * 16 + tr * 4;      // this lane's first token in tile
    const int pk   = tid >> 4;               // staging: col within chunk (base)
    const int pdg  = tid & 15;               // staging: d-group
    const int psw  = pdg & 7;                // staging swizzle = (d>>2)&7 = dg&7

    #pragma unroll
    for (int mat = 0; mat < 3; ++mat) {
        const float* W = ((mat == 0) ? wq : (mat == 1) ? wk : wv)
                         + (size_t)m * KR * DDIM;
        int* G = (mat == 0) ? g_qid : (mat == 1) ? g_kid : g_vid;

        float bmax[4]; int bidx[4];
        #pragma unroll
        for (int t = 0; t < 4; ++t) { bmax[t] = -3.402823466e38f; bidx[t] = 0; }

        __syncthreads();   // previous mat's compute done (also covers x staging)
        // stage chunk 0
        #pragma unroll
        for (int j = 0; j < 4; ++j) {
            int k = pk + 16 * j;
            float4 v = *reinterpret_cast<const float4*>(
                W + (size_t)k * DDIM + pdg * 4);
            int bi = ((((k >> 3) ^ psw) << 3) + (k & 7));
            wsS[(pdg * 4 + 0) * KC + bi] = v.x;
            wsS[(pdg * 4 + 1) * KC + bi] = v.y;
            wsS[(pdg * 4 + 2) * KC + bi] = v.z;
            wsS[(pdg * 4 + 3) * KC + bi] = v.w;
        }
        __syncthreads();

        for (int ch = 0; ch < KR / KC; ++ch) {
            // prefetch next chunk into registers
            float4 pf[4];
            if (ch + 1 < KR / KC) {
                #pragma unroll
                for (int j = 0; j < 4; ++j) {
                    int k = (ch + 1) * KC + pk + 16 * j;
                    pf[j] = *reinterpret_cast<const float4*>(
                        W + (size_t)k * DDIM + pdg * 4);
                }
            }

            uint64_t acc[4][4];
            #pragma unroll
            for (int t = 0; t < 4; ++t)
                #pragma unroll
                for (int c = 0; c < 4; ++c) acc[t][c] = 0ull;

            #pragma unroll 8
            for (int d = 0; d < DDIM; ++d) {
                float4 xv = *reinterpret_cast<const float4*>(&xsT[d * TT + wtok]);
                uint64_t x0 = dup2(xv.x), x1 = dup2(xv.y),
                         x2 = dup2(xv.z), x3 = dup2(xv.w);
                const ulonglong2* wp = reinterpret_cast<const ulonglong2*>(
                    &wsS[d * KC + ((cr ^ ((d >> 2) & 7)) << 3)]);
                ulonglong2 wa = wp[0];   // col pairs 0,1
                ulonglong2 wb = wp[1];   // col pairs 2,3
                acc[0][0] = fma2(x0, wa.x, acc[0][0]);
                acc[0][1] = fma2(x0, wa.y, acc[0][1]);
                acc[0][2] = fma2(x0, wb.x, acc[0][2]);
                acc[0][3] = fma2(x0, wb.y, acc[0][3]);
                acc[1][0] = fma2(x1, wa.x, acc[1][0]);
                acc[1][1] = fma2(x1, wa.y, acc[1][1]);
                acc[1][2] = fma2(x1, wb.x, acc[1][2]);
                acc[1][3] = fma2(x1, wb.y, acc[1][3]);
                acc[2][0] = fma2(x2, wa.x, acc[2][0]);
                acc[2][1] = fma2(x2, wa.y, acc[2][1]);
                acc[2][2] = fma2(x2, wb.x, acc[2][2]);
                acc[2][3] = fma2(x2, wb.y, acc[2][3]);
                acc[3][0] = fma2(x3, wa.x, acc[3][0]);
                acc[3][1] = fma2(x3, wa.y, acc[3][1]);
                acc[3][2] = fma2(x3, wb.x, acc[3][2]);
                acc[3][3] = fma2(x3, wb.y, acc[3][3]);
            }

            // running argmax (ascending col order -> '>' keeps first occurrence)
            int cb = ch * KC + cr * 8;
            #pragma unroll
            for (int t = 0; t < 4; ++t) {
                #pragma unroll
                for (int c = 0; c < 4; ++c) {
                    float lo = __uint_as_float((uint32_t)acc[t][c]);
                    float hi = __uint_as_float((uint32_t)(acc[t][c] >> 32));
                    int col = cb + c * 2;
                    if (lo > bmax[t]) { bmax[t] = lo; bidx[t] = col; }
                    if (hi > bmax[t]) { bmax[t] = hi; bidx[t] = col + 1; }
                }
            }

            __syncthreads();
            if (ch + 1 < KR / KC) {
                #pragma unroll
                for (int j = 0; j < 4; ++j) {
                    int k = pk + 16 * j;
                    int bi = ((((k >> 3) ^ psw) << 3) + (k & 7));
                    wsS[(pdg * 4 + 0) * KC + bi] = pf[j].x;
                    wsS[(pdg * 4 + 1) * KC + bi] = pf[j].y;
                    wsS[(pdg * 4 + 2) * KC + bi] = pf[j].z;
                    wsS[(pdg * 4 + 3) * KC + bi] = pf[j].w;
                }
            }
            __syncthreads();
        }

        // reduce argmax across the 8 cr-lanes (tie -> smaller index)
        #pragma unroll
        for (int t = 0; t < 4; ++t) {
            #pragma unroll
            for (int off = 1; off < 8; off <<= 1) {
                float om = __shfl_xor_sync(0xffffffffu, bmax[t], off, 32);
                int   oi = __shfl_xor_sync(0xffffffffu, bidx[t], off, 32);
                if (om > bmax[t] || (om == bmax[t] && oi < bidx[t])) {
                    bmax[t] = om; bidx[t] = oi;
                }
            }
        }
        if (cr == 0) {
            #pragma unroll
            for (int t = 0; t < 4; ++t)
                G[m * TOK + t0 + wtok + t] = bidx[t];
        }
    }
}

// ---------------------------------------------------------------------------
// Kernel 2: tau matching via bucketed counting sort. grid=NHEAD, block=256.
// tau[t] = largest t'<t with k[t']==q[t]; bucket positions of each k id,
// sort (avg bucket size 2), then scan bucket of q[t] from the top.
// ---------------------------------------------------------------------------
__global__ __launch_bounds__(256) void match_kernel()
{
    __shared__ int cnt[KR];          // counters, then reused as scatter cursor
    __shared__ int bstart[KR + 1];
    __shared__ int kpos[TOK];
    __shared__ int wsum[8];

    const int m = blockIdx.x, tid = threadIdx.x;
    const int lane = tid & 31, wid = tid >> 5;
    const int base = m * TOK;

    for (int i = tid; i < KR; i += 256) cnt[i] = 0;
    __syncthreads();
    for (int t = tid; t < TOK; t += 256) atomicAdd(&cnt[g_kid[base + t]], 1);
    __syncthreads();

    // exclusive prefix over 1024 counters (4 per thread)
    int c0 = cnt[tid * 4], c1 = cnt[tid * 4 + 1],
        c2 = cnt[tid * 4 + 2], c3 = cnt[tid * 4 + 3];
    int tot = c0 + c1 + c2 + c3;
    int incl = tot;
    #pragma unroll
    for (int off = 1; off < 32; off <<= 1) {
        int nv = __shfl_up_sync(0xffffffffu, incl, off, 32);
        if (lane >= off) incl += nv;
    }
    if (lane == 31) wsum[wid] = incl;
    __syncthreads();
    if (tid == 0) {
        int r = 0;
        #pragma unroll
        for (int w = 0; w < 8; ++w) { int v = wsum[w]; wsum[w] = r; r += v; }
    }
    __syncthreads();
    int ex = incl - tot + wsum[wid];
    bstart[tid * 4]     = ex;
    bstart[tid * 4 + 1] = ex + c0;
    bstart[tid * 4 + 2] = ex + c0 + c1;
    bstart[tid * 4 + 3] = ex + c0 + c1 + c2;
    if (tid == 0) bstart[KR] = TOK;
    __syncthreads();
    // reuse cnt as scatter cursors
    cnt[tid * 4]     = ex;
    cnt[tid * 4 + 1] = ex + c0;
    cnt[tid * 4 + 2] = ex + c0 + c1;
    cnt[tid * 4 + 3] = ex + c0 + c1 + c2;
    __syncthreads();

    for (int t = tid; t < TOK; t += 256) {
        int k = g_kid[base + t];
        int p = atomicAdd(&cnt[k], 1);
        kpos[p] = t;
    }
    __syncthreads();

    // sort each bucket ascending (tiny buckets; disjoint per thread)
    for (int b = tid; b < KR; b += 256) {
        int lo = bstart[b], hi = bstart[b + 1];
        for (int i = lo + 1; i < hi; ++i) {
            int v = kpos[i], j = i - 1;
            while (j >= lo && kpos[j] > v) { kpos[j + 1] = kpos[j]; --j; }
            kpos[j + 1] = v;
        }
    }
    __syncthreads();

    for (int t = tid; t < TOK; t += 256) {
        int q = g_qid[base + t];
        int lo = bstart[q], hi = bstart[q + 1];
        int best = -1;
        for (int i = hi - 1; i >= lo; --i) {
            if (kpos[i] < t) { best = kpos[i]; break; }
        }
        g_row[base + t] = (best >= 0) ? (g_vid[base + best] + 1) : 0;
    }
}

// ---------------------------------------------------------------------------
// Kernel 3: embedding gather. grid = (TOK/128, NHEAD), block = 256.
// ---------------------------------------------------------------------------
__global__ __launch_bounds__(256) void gather_kernel(
    const float* __restrict__ emb, float* __restrict__ out)
{
    const int m = blockIdx.y, t0 = blockIdx.x * 128;
    const float* E = emb + (size_t)m * (KR + 1) * DDIM;
    for (int j = threadIdx.x; j < 128 * 16; j += 256) {
        int t = j >> 4, dg = j & 15;
        int row = g_row[m * TOK + t0 + t];
        float4 v;
        if (row) {
            v = *reinterpret_cast<const float4*>(E + (size_t)row * DDIM + dg * 4);
        } else {
            v = make_float4(0.f, 0.f, 0.f, 0.f);   // padding row is zero
        }
        *reinterpret_cast<float4*>(out + (size_t)(t0 + t) * CDIM + m * DDIM + dg * 4) = v;
    }
}

// ---------------------------------------------------------------------------
extern "C" void kernel_launch(void* const* d_in, const int* in_sizes, int n_in,
                              void* d_out, int out_size)
{
    (void)in_sizes; (void)n_in; (void)out_size;
    const float* x   = (const float*)d_in[0];
    const float* wq  = (const float*)d_in[1];
    const float* wk  = (const float*)d_in[2];
    const float* wv  = (const float*)d_in[3];
    const float* emb = (const float*)d_in[4];
    float* out = (float*)d_out;

    dim3 g1(TOK / TT, NHEAD);
    route_kernel<<<g1, 256>>>(x, wq, wk, wv);
    match_kernel<<<NHEAD, 256>>>();
    dim3 g3(TOK / 128, NHEAD);
    gather_kernel<<<g3, 256>>>(emb, out);
}

// round 4
// speedup vs baseline: 1.6875x; 1.5550x over previous
#include <cuda_runtime.h>
#include <cstdint>

#define TOK   2048
#define CDIM  2048
#define NHEAD 32
#define DDIM  64
#define KR    1024

#define CTOK  256            // tokens per CTA
#define NTPM  128            // 8-col n-tiles per matrix (1024/8)
#define NTT   (3 * NTPM)     // 384 n-tiles total (q,k,v)
#define GSZ   8              // n-tiles per pipeline group
#define NGRP  (NTT / GSZ)    // 48
#define NT_B  4096           // bytes per n-tile (8 ksteps x 2 splits x 256B)
#define GRP_B (GSZ * NT_B)   // 32 KB

#define SM_XPIT 68           // x smem pitch (floats)
#define SM_B    (CTOK * SM_XPIT * 4)          // 69632
#define SM_TOTAL (SM_B + 2 * GRP_B)           // 135168

__device__ int g_qid[NHEAD * TOK];
__device__ int g_kid[NHEAD * TOK];
__device__ int g_vid[NHEAD * TOK];
__device__ int g_row[NHEAD * TOK];
// W pre-split to tf32 hi/lo, fragment-major: [mat][head][ntile][kstep][split][lane][2]
__device__ __align__(16) uint8_t g_wtf[(size_t)3 * NHEAD * NTPM * NT_B];   // 48 MB

// ---------------- helpers ----------------
static __device__ __forceinline__ uint32_t s2u(const void* p) {
    uint32_t a;
    asm("{ .reg .u64 t; cvta.to.shared.u64 t, %1; cvt.u32.u64 %0, t; }"
        : "=r"(a) : "l"(p));
    return a;
}
static __device__ __forceinline__ uint32_t tf32c(float f) {
    uint32_t r; asm("cvt.rna.tf32.f32 %0, %1;" : "=r"(r) : "f"(f)); return r;
}
static __device__ __forceinline__ void mma_tf32(float* d, const uint32_t* a,
                                                uint32_t b0, uint32_t b1) {
    asm volatile("mma.sync.aligned.m16n8k8.row.col.f32.tf32.tf32.f32 "
                 "{%0,%1,%2,%3}, {%4,%5,%6,%7}, {%8,%9}, {%0,%1,%2,%3};"
                 : "+f"(d[0]), "+f"(d[1]), "+f"(d[2]), "+f"(d[3])
                 : "r"(a[0]), "r"(a[1]), "r"(a[2]), "r"(a[3]),
                   "r"(b0), "r"(b1));
}
static __device__ __forceinline__ void cp16(uint32_t d, const void* s) {
    asm volatile("cp.async.cg.shared.global [%0], [%1], 16;"
                 :: "r"(d), "l"(s) : "memory");
}
#define CP_COMMIT() asm volatile("cp.async.commit_group;" ::: "memory")
#define CP_WAIT1()  asm volatile("cp.async.wait_group 1;" ::: "memory")
#define CP_WAIT0()  asm volatile("cp.async.wait_group 0;" ::: "memory")

// ---------------------------------------------------------------------------
// Prepass: split W into tf32 hi/lo, fragment-major layout, coalesced writes.
// flat id bits: [mat][head][ntl][ks][s][lane]; each thread writes one 8B pair.
// ---------------------------------------------------------------------------
__global__ __launch_bounds__(256) void split_w_kernel(
    const float* __restrict__ wq, const float* __restrict__ wk,
    const float* __restrict__ wv)
{
    uint32_t id = blockIdx.x * 256u + threadIdx.x;
    uint32_t lane = id & 31u;
    uint32_t s    = (id >> 5) & 1u;
    uint32_t ks   = (id >> 6) & 7u;
    uint32_t ntl  = (id >> 9) & 127u;
    uint32_t head = (id >> 16) & 31u;
    uint32_t mat  = id >> 21;
    const float* W = (mat == 0) ? wq : (mat == 1) ? wk : wv;
    int col = (int)(ntl * 8 + (lane >> 2));
    int k   = (int)(ks * 8 + (lane & 3));
    size_t off = ((size_t)head * KR + col) * DDIM + k;
    float a = W[off], b = W[off + 4];
    uint32_t ra, rb;
    if (s == 0) {
        ra = tf32c(a); rb = tf32c(b);
    } else {
        uint32_t ha = tf32c(a), hb = tf32c(b);
        ra = tf32c(a - __uint_as_float(ha));
        rb = tf32c(b - __uint_as_float(hb));
    }
    uint2 v; v.x = ra; v.y = rb;
    *reinterpret_cast<uint2*>(g_wtf + (size_t)id * 8) = v;
}

// ---------------------------------------------------------------------------
// Route kernel: 3xTF32 mma.sync argmax-GEMM.
// grid = (TOK/CTOK, NHEAD) = (8, 32), block = 256 (8 warps x 32 tokens).
// ---------------------------------------------------------------------------
__global__ __launch_bounds__(256, 1) void tc_route_kernel(const float* __restrict__ x)
{
    extern __shared__ uint8_t smem[];
    float* xs = reinterpret_cast<float*>(smem);
    const uint32_t sbB = s2u(smem) + SM_B;

    const int tid = threadIdx.x, lane = tid & 31, wid = tid >> 5;
    const int m = blockIdx.y;
    const int t0 = blockIdx.x * CTOK;

    // stage x tile [CTOK][64] (pitch 68)
    for (int i = tid; i < CTOK * 16; i += 256) {
        int t = i >> 4, c = i & 15;
        float4 v = *reinterpret_cast<const float4*>(
            x + (size_t)(t0 + t) * CDIM + m * DDIM + c * 4);
        *reinterpret_cast<float4*>(&xs[t * SM_XPIT + c * 4]) = v;
    }
    __syncthreads();

    // build A fragments (tf32 hi/lo) in registers: 2 m-tiles x 8 ksteps x 4 regs
    uint32_t ah[2][8][4], am[2][8][4];
    const int r0 = wid * 32 + (lane >> 2);
    #pragma unroll
    for (int mt = 0; mt < 2; ++mt)
        #pragma unroll
        for (int ks = 0; ks < 8; ++ks)
            #pragma unroll
            for (int e = 0; e < 4; ++e) {
                int row = r0 + mt * 16 + (e & 1) * 8;
                int col = ks * 8 + (lane & 3) + (e >> 1) * 4;
                float v = xs[row * SM_XPIT + col];
                uint32_t h = tf32c(v);
                ah[mt][ks][e] = h;
                am[mt][ks][e] = tf32c(v - __uint_as_float(h));
            }

    // pipeline staging
    auto stage = [&](int g2) {
        int F0 = g2 * GSZ;
        int mat = F0 >> 7, ntl0 = F0 & (NTPM - 1);
        const uint8_t* src = g_wtf
            + (((size_t)mat * NHEAD + m) * NTPM + ntl0) * NT_B + tid * 16;
        uint32_t dst = sbB + (uint32_t)(g2 & 1) * GRP_B + tid * 16;
        #pragma unroll
        for (int j = 0; j < 8; ++j)
            cp16(dst + j * 4096u, src + (size_t)j * 4096);
    };

    float bmax[4]; int bidx[4];
    #pragma unroll
    for (int sl = 0; sl < 4; ++sl) { bmax[sl] = -3.402823466e38f; bidx[sl] = 0; }

    stage(0); CP_COMMIT();

    #pragma unroll 1
    for (int g = 0; g < NGRP; ++g) {
        if (g + 1 < NGRP) { stage(g + 1); CP_COMMIT(); CP_WAIT1(); }
        else              { CP_WAIT0(); }
        __syncthreads();

        const uint32_t bb = sbB + (uint32_t)(g & 1) * GRP_B + (uint32_t)lane * 8u;
        #pragma unroll 1
        for (int ntg = 0; ntg < GSZ; ++ntg) {
            const int F = g * GSZ + ntg;
            float d0[4] = {0.f, 0.f, 0.f, 0.f};
            float d1[4] = {0.f, 0.f, 0.f, 0.f};
            const uint32_t tb = bb + (uint32_t)ntg * NT_B;
            #pragma unroll
            for (int ks = 0; ks < 8; ++ks) {
                uint32_t bh0, bh1, bm0, bm1;
                asm volatile("ld.shared.v2.b32 {%0,%1}, [%2];"
                             : "=r"(bh0), "=r"(bh1) : "r"(tb + ks * 512u));
                asm volatile("ld.shared.v2.b32 {%0,%1}, [%2];"
                             : "=r"(bm0), "=r"(bm1) : "r"(tb + ks * 512u + 256u));
                mma_tf32(d0, ah[0][ks], bh0, bh1);   // hh
                mma_tf32(d0, am[0][ks], bh0, bh1);   // lh
                mma_tf32(d0, ah[0][ks], bm0, bm1);   // hl
                mma_tf32(d1, ah[1][ks], bh0, bh1);
                mma_tf32(d1, am[1][ks], bh0, bh1);
                mma_tf32(d1, ah[1][ks], bm0, bm1);
            }
            // running per-token argmax; cols ascend -> strict '>' keeps first
            const int cb = (F & (NTPM - 1)) * 8 + 2 * (lane & 3);
            if (d0[0] > bmax[0]) { bmax[0] = d0[0]; bidx[0] = cb; }
            if (d0[1] > bmax[0]) { bmax[0] = d0[1]; bidx[0] = cb + 1; }
            if (d0[2] > bmax[1]) { bmax[1] = d0[2]; bidx[1] = cb; }
            if (d0[3] > bmax[1]) { bmax[1] = d0[3]; bidx[1] = cb + 1; }
            if (d1[0] > bmax[2]) { bmax[2] = d1[0]; bidx[2] = cb; }
            if (d1[1] > bmax[2]) { bmax[2] = d1[1]; bidx[2] = cb + 1; }
            if (d1[2] > bmax[3]) { bmax[3] = d1[2]; bidx[3] = cb; }
            if (d1[3] > bmax[3]) { bmax[3] = d1[3]; bidx[3] = cb + 1; }

            if (((F + 1) & (NTPM - 1)) == 0) {      // matrix boundary
                const int mat = F >> 7;
                int* G = (mat == 0) ? g_qid : (mat == 1) ? g_kid : g_vid;
                #pragma unroll
                for (int sl = 0; sl < 4; ++sl) {
                    float bv = bmax[sl]; int bi = bidx[sl];
                    #pragma unroll
                    for (int off = 1; off < 4; off <<= 1) {
                        float om = __shfl_xor_sync(0xffffffffu, bv, off, 32);
                        int   oi = __shfl_xor_sync(0xffffffffu, bi, off, 32);
                        if (om > bv || (om == bv && oi < bi)) { bv = om; bi = oi; }
                    }
                    if ((lane & 3) == 0)
                        G[m * TOK + t0 + wid * 32 + (sl >> 1) * 16
                          + (lane >> 2) + (sl & 1) * 8] = bi;
                    bmax[sl] = -3.402823466e38f; bidx[sl] = 0;
                }
            }
        }
        __syncthreads();   // all warps done reading buf[g&1] before restage
    }
}

// ---------------------------------------------------------------------------
// tau matching via bucketed counting sort. grid=NHEAD, block=256.
// ---------------------------------------------------------------------------
__global__ __launch_bounds__(256) void match_kernel()
{
    __shared__ int cnt[KR];
    __shared__ int bstart[KR + 1];
    __shared__ int kpos[TOK];
    __shared__ int wsum[8];

    const int m = blockIdx.x, tid = threadIdx.x;
    const int lane = tid & 31, wid = tid >> 5;
    const int base = m * TOK;

    for (int i = tid; i < KR; i += 256) cnt[i] = 0;
    __syncthreads();
    for (int t = tid; t < TOK; t += 256) atomicAdd(&cnt[g_kid[base + t]], 1);
    __syncthreads();

    int c0 = cnt[tid * 4], c1 = cnt[tid * 4 + 1],
        c2 = cnt[tid * 4 + 2], c3 = cnt[tid * 4 + 3];
    int tot = c0 + c1 + c2 + c3;
    int incl = tot;
    #pragma unroll
    for (int off = 1; off < 32; off <<= 1) {
        int nv = __shfl_up_sync(0xffffffffu, incl, off, 32);
        if (lane >= off) incl += nv;
    }
    if (lane == 31) wsum[wid] = incl;
    __syncthreads();
    if (tid == 0) {
        int r = 0;
        #pragma unroll
        for (int w = 0; w < 8; ++w) { int v = wsum[w]; wsum[w] = r; r += v; }
    }
    __syncthreads();
    int ex = incl - tot + wsum[wid];
    bstart[tid * 4]     = ex;
    bstart[tid * 4 + 1] = ex + c0;
    bstart[tid * 4 + 2] = ex + c0 + c1;
    bstart[tid * 4 + 3] = ex + c0 + c1 + c2;
    if (tid == 0) bstart[KR] = TOK;
    __syncthreads();
    cnt[tid * 4]     = ex;
    cnt[tid * 4 + 1] = ex + c0;
    cnt[tid * 4 + 2] = ex + c0 + c1;
    cnt[tid * 4 + 3] = ex + c0 + c1 + c2;
    __syncthreads();

    for (int t = tid; t < TOK; t += 256) {
        int k = g_kid[base + t];
        int p = atomicAdd(&cnt[k], 1);
        kpos[p] = t;
    }
    __syncthreads();

    for (int b = tid; b < KR; b += 256) {
        int lo = bstart[b], hi = bstart[b + 1];
        for (int i = lo + 1; i < hi; ++i) {
            int v = kpos[i], j = i - 1;
            while (j >= lo && kpos[j] > v) { kpos[j + 1] = kpos[j]; --j; }
            kpos[j + 1] = v;
        }
    }
    __syncthreads();

    for (int t = tid; t < TOK; t += 256) {
        int q = g_qid[base + t];
        int lo = bstart[q], hi = bstart[q + 1];
        int best = -1;
        for (int i = hi - 1; i >= lo; --i) {
            if (kpos[i] < t) { best = kpos[i]; break; }
        }
        g_row[base + t] = (best >= 0) ? (g_vid[base + best] + 1) : 0;
    }
}

// ---------------------------------------------------------------------------
// Embedding gather. grid = (TOK/128, NHEAD), block = 256.
// ---------------------------------------------------------------------------
__global__ __launch_bounds__(256) void gather_kernel(
    const float* __restrict__ emb, float* __restrict__ out)
{
    const int m = blockIdx.y, t0 = blockIdx.x * 128;
    const float* E = emb + (size_t)m * (KR + 1) * DDIM;
    for (int j = threadIdx.x; j < 128 * 16; j += 256) {
        int t = j >> 4, dg = j & 15;
        int row = g_row[m * TOK + t0 + t];
        float4 v;
        if (row) {
            v = *reinterpret_cast<const float4*>(E + (size_t)row * DDIM + dg * 4);
        } else {
            v = make_float4(0.f, 0.f, 0.f, 0.f);   // padding row is zero
        }
        *reinterpret_cast<float4*>(out + (size_t)(t0 + t) * CDIM + m * DDIM + dg * 4) = v;
    }
}

// ---------------------------------------------------------------------------
extern "C" void kernel_launch(void* const* d_in, const int* in_sizes, int n_in,
                              void* d_out, int out_size)
{
    (void)in_sizes; (void)n_in; (void)out_size;
    const float* x   = (const float*)d_in[0];
    const float* wq  = (const float*)d_in[1];
    const float* wk  = (const float*)d_in[2];
    const float* wv  = (const float*)d_in[3];
    const float* emb = (const float*)d_in[4];
    float* out = (float*)d_out;

    cudaFuncSetAttribute(tc_route_kernel,
                         cudaFuncAttributeMaxDynamicSharedMemorySize, SM_TOTAL);

    split_w_kernel<<<(3u << 21) / 256, 256>>>(wq, wk, wv);
    dim3 g1(TOK / CTOK, NHEAD);
    tc_route_kernel<<<g1, 256, SM_TOTAL>>>(x);
    match_kernel<<<NHEAD, 256>>>();
    dim3 g3(TOK / 128, NHEAD);
    gather_kernel<<<g3, 256>>>(emb, out);
}

// round 5
// speedup vs baseline: 4.7615x; 2.8216x over previous
#include <cuda_runtime.h>
#include <cuda_fp16.h>
#include <cstdint>

#define TOK   2048
#define CDIM  2048
#define NHEAD 32
#define DDIM  64
#define KR    1024

#define CTOK  256            // tokens per CTA
#define NTPM  128            // 8-col n-tiles per matrix
#define NTT   (3 * NTPM)     // 384 n-tiles (q,k,v)
#define GSZ   8              // n-tiles per pipeline group
#define NGRP  (NTT / GSZ)    // 48
#define NT_B  2048           // bytes per n-tile: 4 ksteps x 2 splits x 32 lanes x 8B
#define GRP_B (GSZ * NT_B)   // 16 KB

#define SM_XPIT 68
#define SM_B    (CTOK * SM_XPIT * 4)          // 69632
#define SM_TOTAL (SM_B + 2 * GRP_B)           // 102400 -> 2 CTAs/SM

__device__ int g_qid[NHEAD * TOK];
__device__ int g_kid[NHEAD * TOK];
__device__ int g_vid[NHEAD * TOK];
__device__ int g_row[NHEAD * TOK];
// W pre-split to fp16 hi/lo, fragment-major: [mat][head][ntl][ks][s][lane][b0b1]
__device__ __align__(16) uint8_t g_whf[(size_t)3 * NHEAD * NTPM * NT_B];   // 24 MB

// ---------------- helpers ----------------
static __device__ __forceinline__ uint32_t s2u(const void* p) {
    uint32_t a;
    asm("{ .reg .u64 t; cvta.to.shared.u64 t, %1; cvt.u32.u64 %0, t; }"
        : "=r"(a) : "l"(p));
    return a;
}
static __device__ __forceinline__ uint32_t h2u(__half2 h) {
    uint32_t u; asm("mov.b32 %0, %1;" : "=r"(u) : "r"(*(uint32_t*)&h)); return u;
}
static __device__ __forceinline__ void mma_f16(float* d, const uint32_t* a,
                                               uint32_t b0, uint32_t b1) {
    asm volatile("mma.sync.aligned.m16n8k16.row.col.f32.f16.f16.f32 "
                 "{%0,%1,%2,%3}, {%4,%5,%6,%7}, {%8,%9}, {%0,%1,%2,%3};"
                 : "+f"(d[0]), "+f"(d[1]), "+f"(d[2]), "+f"(d[3])
                 : "r"(a[0]), "r"(a[1]), "r"(a[2]), "r"(a[3]),
                   "r"(b0), "r"(b1));
}
static __device__ __forceinline__ void cp16(uint32_t d, const void* s) {
    asm volatile("cp.async.cg.shared.global [%0], [%1], 16;"
                 :: "r"(d), "l"(s) : "memory");
}
#define CP_COMMIT() asm volatile("cp.async.commit_group;" ::: "memory")
#define CP_WAIT1()  asm volatile("cp.async.wait_group 1;" ::: "memory")
#define CP_WAIT0()  asm volatile("cp.async.wait_group 0;" ::: "memory")

// split one float pair into packed fp16 hi / lo
static __device__ __forceinline__ void split2(float2 v, uint32_t& h, uint32_t& l) {
    __half2 hh = __float22half2_rn(v);
    float2 hf = __half22float2(hh);
    __half2 ll = __float22half2_rn(make_float2(v.x - hf.x, v.y - hf.y));
    h = h2u(hh); l = h2u(ll);
}

// ---------------------------------------------------------------------------
// Prepass: split W into fp16 hi/lo, fragment-major.
// id bits: lane[0:5) s[5] ks[6:8) ntl[8:15) head[15:20) mat[20:22)
// ---------------------------------------------------------------------------
__global__ __launch_bounds__(256) void split_w_kernel(
    const float* __restrict__ wq, const float* __restrict__ wk,
    const float* __restrict__ wv)
{
    uint32_t id = blockIdx.x * 256u + threadIdx.x;
    uint32_t lane = id & 31u;
    uint32_t s    = (id >> 5) & 1u;
    uint32_t ks   = (id >> 6) & 3u;
    uint32_t ntl  = (id >> 8) & 127u;
    uint32_t head = (id >> 15) & 31u;
    uint32_t mat  = id >> 20;
    const float* W = (mat == 0) ? wq : (mat == 1) ? wk : wv;
    int col = (int)(ntl * 8 + (lane >> 2));
    int k0  = (int)(ks * 16 + 2 * (lane & 3));
    size_t off = ((size_t)head * KR + col) * DDIM + k0;
    float2 v0 = *reinterpret_cast<const float2*>(W + off);
    float2 v1 = *reinterpret_cast<const float2*>(W + off + 8);
    uint32_t h0, l0, h1, l1;
    split2(v0, h0, l0);
    split2(v1, h1, l1);
    uint2 o;
    if (s == 0) { o.x = h0; o.y = h1; } else { o.x = l0; o.y = l1; }
    *reinterpret_cast<uint2*>(g_whf + (size_t)id * 8) = o;
}

// ---------------------------------------------------------------------------
// Route kernel: 2-split fp16 mma.sync argmax-GEMM.
// grid = (8, 32), block = 256 (8 warps x 32 tokens), 2 CTAs/SM -> 1 wave.
// ---------------------------------------------------------------------------
__global__ __launch_bounds__(256, 2) void tc_route_kernel(const float* __restrict__ x)
{
    extern __shared__ uint8_t smem[];
    float* xs = reinterpret_cast<float*>(smem);
    const uint32_t sbB = s2u(smem) + SM_B;

    const int tid = threadIdx.x, lane = tid & 31, wid = tid >> 5;
    const int m = blockIdx.y;
    const int t0 = blockIdx.x * CTOK;

    // stage x tile [CTOK][64] (pitch 68)
    for (int i = tid; i < CTOK * 16; i += 256) {
        int t = i >> 4, c = i & 15;
        float4 v = *reinterpret_cast<const float4*>(
            x + (size_t)(t0 + t) * CDIM + m * DDIM + c * 4);
        *reinterpret_cast<float4*>(&xs[t * SM_XPIT + c * 4]) = v;
    }
    __syncthreads();

    // A fragments (fp16 hi/lo): 2 m-tiles x 4 ksteps x 4 regs, packed half2
    uint32_t ah[2][4][4], al[2][4][4];
    const int r0 = wid * 32 + (lane >> 2);
    #pragma unroll
    for (int mt = 0; mt < 2; ++mt)
        #pragma unroll
        for (int ks = 0; ks < 4; ++ks)
            #pragma unroll
            for (int e = 0; e < 4; ++e) {
                int row = r0 + mt * 16 + (e & 1) * 8;
                int kc  = ks * 16 + 2 * (lane & 3) + (e >> 1) * 8;
                float2 v = *reinterpret_cast<const float2*>(&xs[row * SM_XPIT + kc]);
                split2(v, ah[mt][ks][e], al[mt][ks][e]);
            }

    auto stage = [&](int g2) {
        int F0 = g2 * GSZ;
        int mat = F0 >> 7, ntl0 = F0 & (NTPM - 1);
        const uint8_t* src = g_whf
            + (((size_t)mat * NHEAD + m) * NTPM + ntl0) * NT_B + tid * 16;
        uint32_t dst = sbB + (uint32_t)(g2 & 1) * GRP_B + tid * 16;
        #pragma unroll
        for (int j = 0; j < 4; ++j)
            cp16(dst + j * 4096u, src + (size_t)j * 4096);
    };

    float bmax[4]; int bidx[4];
    #pragma unroll
    for (int sl = 0; sl < 4; ++sl) { bmax[sl] = -3.402823466e38f; bidx[sl] = 0; }

    stage(0); CP_COMMIT();

    #pragma unroll 1
    for (int g = 0; g < NGRP; ++g) {
        if (g + 1 < NGRP) { stage(g + 1); CP_COMMIT(); CP_WAIT1(); }
        else              { CP_WAIT0(); }
        __syncthreads();

        const uint32_t bb = sbB + (uint32_t)(g & 1) * GRP_B + (uint32_t)lane * 8u;
        #pragma unroll 1
        for (int ntg = 0; ntg < GSZ; ++ntg) {
            const int F = g * GSZ + ntg;
            float d0[4] = {0.f, 0.f, 0.f, 0.f};
            float d1[4] = {0.f, 0.f, 0.f, 0.f};
            const uint32_t tb = bb + (uint32_t)ntg * NT_B;
            #pragma unroll
            for (int ks = 0; ks < 4; ++ks) {
                uint32_t bh0, bh1, bl0, bl1;
                asm volatile("ld.shared.v2.b32 {%0,%1}, [%2];"
                             : "=r"(bh0), "=r"(bh1) : "r"(tb + ks * 512u));
                asm volatile("ld.shared.v2.b32 {%0,%1}, [%2];"
                             : "=r"(bl0), "=r"(bl1) : "r"(tb + ks * 512u + 256u));
                mma_f16(d0, ah[0][ks], bh0, bh1);   // hh
                mma_f16(d0, al[0][ks], bh0, bh1);   // lh
                mma_f16(d0, ah[0][ks], bl0, bl1);   // hl
                mma_f16(d1, ah[1][ks], bh0, bh1);
                mma_f16(d1, al[1][ks], bh0, bh1);
                mma_f16(d1, ah[1][ks], bl0, bl1);
            }
            // running per-token argmax; cols ascend -> strict '>' keeps first
            const int cb = (F & (NTPM - 1)) * 8 + 2 * (lane & 3);
            if (d0[0] > bmax[0]) { bmax[0] = d0[0]; bidx[0] = cb; }
            if (d0[1] > bmax[0]) { bmax[0] = d0[1]; bidx[0] = cb + 1; }
            if (d0[2] > bmax[1]) { bmax[1] = d0[2]; bidx[1] = cb; }
            if (d0[3] > bmax[1]) { bmax[1] = d0[3]; bidx[1] = cb + 1; }
            if (d1[0] > bmax[2]) { bmax[2] = d1[0]; bidx[2] = cb; }
            if (d1[1] > bmax[2]) { bmax[2] = d1[1]; bidx[2] = cb + 1; }
            if (d1[2] > bmax[3]) { bmax[3] = d1[2]; bidx[3] = cb; }
            if (d1[3] > bmax[3]) { bmax[3] = d1[3]; bidx[3] = cb + 1; }

            if (((F + 1) & (NTPM - 1)) == 0) {      // matrix boundary
                const int mat = F >> 7;
                int* G = (mat == 0) ? g_qid : (mat == 1) ? g_kid : g_vid;
                #pragma unroll
                for (int sl = 0; sl < 4; ++sl) {
                    float bv = bmax[sl]; int bi = bidx[sl];
                    #pragma unroll
                    for (int off = 1; off < 4; off <<= 1) {
                        float om = __shfl_xor_sync(0xffffffffu, bv, off, 32);
                        int   oi = __shfl_xor_sync(0xffffffffu, bi, off, 32);
                        if (om > bv || (om == bv && oi < bi)) { bv = om; bi = oi; }
                    }
                    if ((lane & 3) == 0)
                        G[m * TOK + t0 + wid * 32 + (sl >> 1) * 16
                          + (lane >> 2) + (sl & 1) * 8] = bi;
                    bmax[sl] = -3.402823466e38f; bidx[sl] = 0;
                }
            }
        }
        __syncthreads();
    }
}

// ---------------------------------------------------------------------------
// tau matching via bucketed counting sort. grid=NHEAD, block=256.
// ---------------------------------------------------------------------------
__global__ __launch_bounds__(256) void match_kernel()
{
    __shared__ int cnt[KR];
    __shared__ int bstart[KR + 1];
    __shared__ int kpos[TOK];
    __shared__ int wsum[8];

    const int m = blockIdx.x, tid = threadIdx.x;
    const int lane = tid & 31, wid = tid >> 5;
    const int base = m * TOK;

    for (int i = tid; i < KR; i += 256) cnt[i] = 0;
    __syncthreads();
    for (int t = tid; t < TOK; t += 256) atomicAdd(&cnt[g_kid[base + t]], 1);
    __syncthreads();

    int c0 = cnt[tid * 4], c1 = cnt[tid * 4 + 1],
        c2 = cnt[tid * 4 + 2], c3 = cnt[tid * 4 + 3];
    int tot = c0 + c1 + c2 + c3;
    int incl = tot;
    #pragma unroll
    for (int off = 1; off < 32; off <<= 1) {
        int nv = __shfl_up_sync(0xffffffffu, incl, off, 32);
        if (lane >= off) incl += nv;
    }
    if (lane == 31) wsum[wid] = incl;
    __syncthreads();
    if (tid == 0) {
        int r = 0;
        #pragma unroll
        for (int w = 0; w < 8; ++w) { int v = wsum[w]; wsum[w] = r; r += v; }
    }
    __syncthreads();
    int ex = incl - tot + wsum[wid];
    bstart[tid * 4]     = ex;
    bstart[tid * 4 + 1] = ex + c0;
    bstart[tid * 4 + 2] = ex + c0 + c1;
    bstart[tid * 4 + 3] = ex + c0 + c1 + c2;
    if (tid == 0) bstart[KR] = TOK;
    __syncthreads();
    cnt[tid * 4]     = ex;
    cnt[tid * 4 + 1] = ex + c0;
    cnt[tid * 4 + 2] = ex + c0 + c1;
    cnt[tid * 4 + 3] = ex + c0 + c1 + c2;
    __syncthreads();

    for (int t = tid; t < TOK; t += 256) {
        int k = g_kid[base + t];
        int p = atomicAdd(&cnt[k], 1);
        kpos[p] = t;
    }
    __syncthreads();

    for (int b = tid; b < KR; b += 256) {
        int lo = bstart[b], hi = bstart[b + 1];
        for (int i = lo + 1; i < hi; ++i) {
            int v = kpos[i], j = i - 1;
            while (j >= lo && kpos[j] > v) { kpos[j + 1] = kpos[j]; --j; }
            kpos[j + 1] = v;
        }
    }
    __syncthreads();

    for (int t = tid; t < TOK; t += 256) {
        int q = g_qid[base + t];
        int lo = bstart[q], hi = bstart[q + 1];
        int best = -1;
        for (int i = hi - 1; i >= lo; --i) {
            if (kpos[i] < t) { best = kpos[i]; break; }
        }
        g_row[base + t] = (best >= 0) ? (g_vid[base + best] + 1) : 0;
    }
}

// ---------------------------------------------------------------------------
// Embedding gather. grid = (TOK/128, NHEAD), block = 256.
// ---------------------------------------------------------------------------
__global__ __launch_bounds__(256) void gather_kernel(
    const float* __restrict__ emb, float* __restrict__ out)
{
    const int m = blockIdx.y, t0 = blockIdx.x * 128;
    const float* E = emb + (size_t)m * (KR + 1) * DDIM;
    for (int j = threadIdx.x; j < 128 * 16; j += 256) {
        int t = j >> 4, dg = j & 15;
        int row = g_row[m * TOK + t0 + t];
        float4 v;
        if (row) {
            v = *reinterpret_cast<const float4*>(E + (size_t)row * DDIM + dg * 4);
        } else {
            v = make_float4(0.f, 0.f, 0.f, 0.f);   // padding row is zero
        }
        *reinterpret_cast<float4*>(out + (size_t)(t0 + t) * CDIM + m * DDIM + dg * 4) = v;
    }
}

// ---------------------------------------------------------------------------
extern "C" void kernel_launch(void* const* d_in, const int* in_sizes, int n_in,
                              void* d_out, int out_size)
{
    (void)in_sizes; (void)n_in; (void)out_size;
    const float* x   = (const float*)d_in[0];
    const float* wq  = (const float*)d_in[1];
    const float* wk  = (const float*)d_in[2];
    const float* wv  = (const float*)d_in[3];
    const float* emb = (const float*)d_in[4];
    float* out = (float*)d_out;

    cudaFuncSetAttribute(tc_route_kernel,
                         cudaFuncAttributeMaxDynamicSharedMemorySize, SM_TOTAL);

    split_w_kernel<<<(3u << 20) / 256, 256>>>(wq, wk, wv);
    dim3 g1(TOK / CTOK, NHEAD);
    tc_route_kernel<<<g1, 256, SM_TOTAL>>>(x);
    match_kernel<<<NHEAD, 256>>>();
    dim3 g3(TOK / 128, NHEAD);
    gather_kernel<<<g3, 256>>>(emb, out);
}